// round 8
// baseline (speedup 1.0000x reference)
#include <cuda_runtime.h>
#include <cstdint>

#define MAX_SAMPLES 512
#define TPB 256
#define CHUNK_C 1024              // count: 4 pts/thread, one float4 per array
#define CHUNK_W 2048              // write: 8 pts/thread
#define ROUNDS_W (CHUNK_W / TPB)  // 8
#define W_PREFIX 32768            // prefix window (>10 sigma above fill point)
#define MAXB 64
#define MAXKC 64                  // max count chunks per batch
#define T_THREADS 1024
#define T_PPT 4
#define T_CHUNK (T_THREADS * T_PPT)

__device__ int g_counts[MAXB * MAXKC * 8];

// Match XLA's non-contracted, left-associated ((x*x)+(y*y))+(z*z).
__device__ __forceinline__ int octant_of(float x, float y, float z) {
    float r2 = __fadd_rn(__fadd_rn(__fmul_rn(x, x), __fmul_rn(y, y)), __fmul_rn(z, z));
    if (!(r2 <= 1.0f)) return -1;
    return ((x >= 0.0f) ? 4 : 0) | ((y >= 0.0f) ? 2 : 0) | ((z >= 0.0f) ? 1 : 0);
}

// ---------------------------------------------------------------------------
// Pass 1: histograms over the prefix window (float4 loads, packed-byte
// counters) + blanket output fill with -1.
// ---------------------------------------------------------------------------
__global__ void count_kernel(const float* __restrict__ pcs, float* __restrict__ out,
                             int N, int bpb_c, int out_count) {
    const int b = blockIdx.x / bpb_c;
    const int k = blockIdx.x % bpb_c;
    const int tid = threadIdx.x;

    for (int j = blockIdx.x * TPB + tid; j < out_count; j += gridDim.x * TPB)
        out[j] = -1.0f;

    const float* __restrict__ xs = pcs + (size_t)b * 3 * N;
    const float* __restrict__ ys = xs + N;
    const float* __restrict__ zs = ys + N;

    const int start = k * CHUNK_C;
    const int end   = min(start + CHUNK_C, N);
    const int i0    = start + tid * 4;

    unsigned lo = 0, hi = 0;   // byte counters: lo = oct 0..3, hi = oct 4..7
    if (i0 + 3 < end) {
        const float4 vx = *reinterpret_cast<const float4*>(xs + i0);
        const float4 vy = *reinterpret_cast<const float4*>(ys + i0);
        const float4 vz = *reinterpret_cast<const float4*>(zs + i0);
        const float px[4] = {vx.x, vx.y, vx.z, vx.w};
        const float py[4] = {vy.x, vy.y, vy.z, vy.w};
        const float pz[4] = {vz.x, vz.y, vz.z, vz.w};
#pragma unroll
        for (int j = 0; j < 4; j++) {
            int o = octant_of(px[j], py[j], pz[j]);
            if (o >= 0) { if (o < 4) lo += 1u << (8 * o); else hi += 1u << (8 * (o - 4)); }
        }
    } else {
        for (int i = i0; i < end && i < i0 + 4; i++) {
            int o = octant_of(xs[i], ys[i], zs[i]);
            if (o >= 0) { if (o < 4) lo += 1u << (8 * o); else hi += 1u << (8 * (o - 4)); }
        }
    }

#pragma unroll
    for (int off = 16; off > 0; off >>= 1) {
        lo += __shfl_down_sync(0xFFFFFFFFu, lo, off);
        hi += __shfl_down_sync(0xFFFFFFFFu, hi, off);
    }

    __shared__ int sh[8];
    if (tid < 8) sh[tid] = 0;
    __syncthreads();
    if ((tid & 31) == 0) {
#pragma unroll
        for (int q = 0; q < 4; q++) {
            unsigned a = (lo >> (8 * q)) & 255u;
            unsigned c = (hi >> (8 * q)) & 255u;
            if (a) atomicAdd(&sh[q], (int)a);
            if (c) atomicAdd(&sh[q + 4], (int)c);
        }
    }
    __syncthreads();
    if (tid < 8)
        g_counts[((size_t)b * MAXKC + k) * 8 + tid] = sh[tid];
}

// ---------------------------------------------------------------------------
// Pass 2: ordered write within the window. float4 loads, octants exchanged
// through shared memory; blocks fully past the fill point read no point data.
// ---------------------------------------------------------------------------
__global__ void write_kernel(const float* __restrict__ pcs, float* __restrict__ out,
                             int N, int bpb_c, int bpb_w, int win_end) {
    const int b = blockIdx.x / bpb_w;
    const int k = blockIdx.x % bpb_w;
    const int tid  = threadIdx.x;
    const int lane = tid & 31;
    const int w    = tid >> 5;

    __shared__ int sh_base[8];
    __shared__ int wcnt[8][9];
    __shared__ int wpre[8][9];
    __shared__ int sh_tot[8];
    __shared__ unsigned char sh_oc[CHUNK_W];

    if (tid < 8) {
        int kc_end = min(2 * k, bpb_c);   // count chunks covering [0, k*CHUNK_W)
        int s = 0;
        for (int kk = 0; kk < kc_end; kk++)
            s += g_counts[((size_t)b * MAXKC + kk) * 8 + tid];
        sh_base[tid] = s;
    }
    __syncthreads();

    int base[8];
    bool full = true;
#pragma unroll
    for (int q = 0; q < 8; q++) {
        base[q] = sh_base[q];
        full = full && (base[q] >= MAX_SAMPLES);
    }
    if (full) return;

    const float* __restrict__ xs = pcs + (size_t)b * 3 * N;
    const float* __restrict__ ys = xs + N;
    const float* __restrict__ zs = ys + N;
    float* __restrict__ out_b = out + (size_t)b * (8 * MAX_SAMPLES);

    const int start = k * CHUNK_W;
    const int end   = min(start + CHUNK_W, win_end);
    const int p     = start + tid * 8;

    // Compute 8 octants per thread, exchange as packed bytes via smem.
    unsigned pk0 = 0, pk1 = 0;
    if (p + 7 < end) {
        const float4 x0 = *reinterpret_cast<const float4*>(xs + p);
        const float4 x1 = *reinterpret_cast<const float4*>(xs + p + 4);
        const float4 y0 = *reinterpret_cast<const float4*>(ys + p);
        const float4 y1 = *reinterpret_cast<const float4*>(ys + p + 4);
        const float4 z0 = *reinterpret_cast<const float4*>(zs + p);
        const float4 z1 = *reinterpret_cast<const float4*>(zs + p + 4);
        const float px[8] = {x0.x, x0.y, x0.z, x0.w, x1.x, x1.y, x1.z, x1.w};
        const float py[8] = {y0.x, y0.y, y0.z, y0.w, y1.x, y1.y, y1.z, y1.w};
        const float pz[8] = {z0.x, z0.y, z0.z, z0.w, z1.x, z1.y, z1.z, z1.w};
#pragma unroll
        for (int j = 0; j < 8; j++) {
            unsigned o = (unsigned)octant_of(px[j], py[j], pz[j]) & 255u;
            if (j < 4) pk0 |= o << (8 * j); else pk1 |= o << (8 * (j - 4));
        }
    } else {
#pragma unroll
        for (int j = 0; j < 8; j++) {
            int i = p + j;
            unsigned o = 255u;   // -1
            if (i < end) o = (unsigned)octant_of(xs[i], ys[i], zs[i]) & 255u;
            if (j < 4) pk0 |= o << (8 * j); else pk1 |= o << (8 * (j - 4));
        }
    }
    *reinterpret_cast<uint2*>(sh_oc + tid * 8) = make_uint2(pk0, pk1);
    __syncthreads();

    const unsigned lt = (1u << lane) - 1u;

#pragma unroll
    for (int r = 0; r < ROUNDS_W; r++) {
        bool done = true;
#pragma unroll
        for (int q = 0; q < 8; q++) done = done && (base[q] >= MAX_SAMPLES);
        if (done) break;

        const int o = (int)(signed char)sh_oc[r * TPB + tid];

        int lane_rank = 0;
#pragma unroll
        for (int q = 0; q < 8; q++) {
            unsigned bal = __ballot_sync(0xFFFFFFFFu, o == q);
            if (o == q)   lane_rank = __popc(bal & lt);
            if (lane == 0) wcnt[w][q] = __popc(bal);
        }
        __syncthreads();                       // (A)

        if (tid < 64) {
            int q  = tid & 7;
            int ww = tid >> 3;
            int s = 0;
            for (int w2 = 0; w2 < ww; w2++) s += wcnt[w2][q];
            wpre[ww][q] = s;
            if (ww == 7) sh_tot[q] = s + wcnt[7][q];
        }
        __syncthreads();                       // (B)

        if (o >= 0) {
            int rank = base[o] + wpre[w][o] + lane_rank;
            if (rank < MAX_SAMPLES)
                out_b[(o << 9) + rank] = (float)(start + r * TPB + tid);
        }
#pragma unroll
        for (int q = 0; q < 8; q++) base[q] += sh_tot[q];
        // reads of sh_tot complete before next round's barrier (A) -> no race
    }
}

// ---------------------------------------------------------------------------
// Pass 3: sequential tail beyond the window (correctness fallback; returns
// immediately for the benchmark distribution).
// ---------------------------------------------------------------------------
__global__ __launch_bounds__(T_THREADS, 1)
void tail_kernel(const float* __restrict__ pcs, float* __restrict__ out,
                 int N, int bpb_c, int tail_start) {
    const int b    = blockIdx.x;
    const int tid  = threadIdx.x;
    const int lane = tid & 31;
    const int w    = tid >> 5;

    __shared__ int sh_base[8];
    __shared__ int warp_cnt[32][9];
    __shared__ int warp_pre[32][9];
    __shared__ int sh_tot[8];

    if (tid < 8) {
        int s = 0;
        for (int kk = 0; kk < bpb_c; kk++)
            s += g_counts[((size_t)b * MAXKC + kk) * 8 + tid];
        sh_base[tid] = s;
    }
    __syncthreads();

    {
        bool full = true;
#pragma unroll
        for (int q = 0; q < 8; q++) full = full && (sh_base[q] >= MAX_SAMPLES);
        if (full) return;
    }

    const float* __restrict__ xs = pcs + (size_t)b * 3 * N;
    const float* __restrict__ ys = xs + N;
    const float* __restrict__ zs = ys + N;
    float* __restrict__ out_b = out + (size_t)b * (8 * MAX_SAMPLES);

    for (int s = tail_start; s < N; s += T_CHUNK) {
        int oc[T_PPT];
#pragma unroll
        for (int q = 0; q < T_PPT; q++) {
            int i = s + q * T_THREADS + tid;
            bool ok = (i < N);
            float x = ok ? xs[i] : 2.0f;
            float y = ok ? ys[i] : 2.0f;
            float z = ok ? zs[i] : 2.0f;
            oc[q] = octant_of(x, y, z);
        }

#pragma unroll
        for (int q = 0; q < T_PPT; q++) {
            const int o = oc[q];
            int lane_rank = 0;
            const unsigned lt = (1u << lane) - 1u;
#pragma unroll
            for (int kk = 0; kk < 8; kk++) {
                unsigned bal = __ballot_sync(0xFFFFFFFFu, o == kk);
                if (o == kk)  lane_rank = __popc(bal & lt);
                if (lane == 0) warp_cnt[w][kk] = __popc(bal);
            }
            __syncthreads();

            if (w < 8) {
                int v   = warp_cnt[lane][w];
                int inc = v;
#pragma unroll
                for (int d = 1; d < 32; d <<= 1) {
                    int nv = __shfl_up_sync(0xFFFFFFFFu, inc, d);
                    if (lane >= d) inc += nv;
                }
                warp_pre[lane][w] = inc - v;
                if (lane == 31) sh_tot[w] = inc;
            }
            __syncthreads();

            if (o >= 0) {
                int rank = sh_base[o] + warp_pre[w][o] + lane_rank;
                if (rank < MAX_SAMPLES)
                    out_b[(o << 9) + rank] = (float)(s + q * T_THREADS + tid);
            }
            __syncthreads();

            if (tid < 8) sh_base[tid] += sh_tot[tid];
            __syncthreads();
        }

        bool full = true;
#pragma unroll
        for (int q = 0; q < 8; q++) full = full && (sh_base[q] >= MAX_SAMPLES);
        if (full) break;
    }
}

// ---------------------------------------------------------------------------
extern "C" void kernel_launch(void* const* d_in, const int* in_sizes, int n_in,
                              void* d_out, int out_size) {
    const float* pcs = (const float*)d_in[0];
    float* out = (float*)d_out;

    int B = out_size / (8 * MAX_SAMPLES);   // 16
    if (B < 1) B = 1;
    if (B > MAXB) B = MAXB;
    int N = in_sizes[0] / (3 * B);          // 200000

    int W = W_PREFIX < N ? W_PREFIX : N;
    int bpb_c = (W + CHUNK_C - 1) / CHUNK_C;      // count chunks per batch (<=32)
    if (bpb_c > MAXKC) bpb_c = MAXKC;
    int win_end = min(bpb_c * CHUNK_C, N);        // window covered by count
    int bpb_w = (win_end + CHUNK_W - 1) / CHUNK_W;
    int tail_start = win_end;

    count_kernel<<<B * bpb_c, TPB>>>(pcs, out, N, bpb_c, B * 8 * MAX_SAMPLES);
    write_kernel<<<B * bpb_w, TPB>>>(pcs, out, N, bpb_c, bpb_w, win_end);
    tail_kernel<<<B, T_THREADS>>>(pcs, out, N, bpb_c, tail_start);
}